// round 13
// baseline (speedup 1.0000x reference)
#include <cuda_runtime.h>
#include <cuda_bf16.h>
#include <cuda_fp16.h>
#include <cstdint>

// Problem constants (fixed by the dataset)
#define NN      50000
#define FDIM    128
#define HEADS   4
#define NGRAPH  64
#define OUTCH   10
#define NEG     0.2f
#define MAXE    800000
#define MAXTOT  (MAXE + NN)   // edges + self loops

// ---------------- device scratch (static, no allocation) ----------------
__device__ __align__(16) __half g_Hh[NN * FDIM];   // gemm output (pre-bias h), fp16
__device__ __align__(16) float  g_P[NN * FDIM];    // ping buffer
__device__ __align__(16) float  g_Q[NN * FDIM];    // pong buffer
__device__ __align__(16) float  g_asrc[NN * HEADS];
__device__ __align__(16) float  g_adst[NN * HEADS];
__device__ __align__(16) float  g_pooled[NGRAPH * FDIM];
// W split into fp16 hi/lo, transposed to [n][k] (per layer, pre-GEMM)
__device__ __align__(16) __half g_Wt_hi[FDIM * FDIM];
__device__ __align__(16) __half g_Wt_lo[FDIM * FDIM];
// CSR by destination (built once per launch; graph static across layers)
__device__ int g_deg[NN];
__device__ int g_off[NN + 1];
__device__ int g_cursor[NN];
__device__ int g_csr_src[MAXTOT];

__device__ __forceinline__ float lrelu(float e) { return e > 0.f ? e : NEG * e; }

__device__ __forceinline__ float* sel_buf(int sel) {
    return sel == 1 ? g_P : g_Q;
}
__device__ __forceinline__ const float* sel_x(const float* ext, int sel) {
    return sel == 0 ? ext : (sel == 1 ? g_P : g_Q);
}

// ================= CSR build (once per launch) =================
__global__ void init_deg() {
    int i = blockIdx.x * blockDim.x + threadIdx.x;
    if (i < NN) g_deg[i] = 1;          // self loop
}
__global__ void count_deg(const int* __restrict__ dsts, int E) {
    int i = blockIdx.x * blockDim.x + threadIdx.x;
    if (i < E) atomicAdd(&g_deg[dsts[i]], 1);
}
// one block, 1024 threads: chunked exclusive scan of g_deg -> g_off, g_cursor
__global__ void scan_deg() {
    __shared__ int part[1024];
    const int CH = (NN + 1023) / 1024;   // 49
    int t = threadIdx.x;
    int base = t * CH;
    int s = 0;
    for (int k = 0; k < CH; k++) {
        int idx = base + k;
        if (idx < NN) s += g_deg[idx];
    }
    part[t] = s;
    __syncthreads();
    for (int off = 1; off < 1024; off <<= 1) {
        int v = (t >= off) ? part[t - off] : 0;
        __syncthreads();
        part[t] += v;
        __syncthreads();
    }
    int run = part[t] - s;     // exclusive start of this chunk
    for (int k = 0; k < CH; k++) {
        int idx = base + k;
        if (idx < NN) {
            g_off[idx]    = run;
            g_cursor[idx] = run;
            run += g_deg[idx];
        }
    }
    if (t == 0) g_off[NN] = part[1023];
}
__global__ void scatter_edges(const int* __restrict__ srcs,
                              const int* __restrict__ dsts, int E, int total) {
    int i = blockIdx.x * blockDim.x + threadIdx.x;
    if (i >= total) return;
    int s, d;
    if (i < E) { s = srcs[i]; d = dsts[i]; }
    else       { s = d = i - E; }
    int pos = atomicAdd(&g_cursor[d], 1);
    g_csr_src[pos] = s;
}

// ========== W -> fp16 hi/lo, transposed [n][k] (per layer) ==========
__global__ void conv_w(const float* __restrict__ W) {
    int i = blockIdx.x * blockDim.x + threadIdx.x;
    if (i >= FDIM * FDIM) return;
    int k = i >> 7, n = i & 127;
    float v = W[i];                       // W[k][n]
    __half h = __float2half_rn(v);
    __half l = __float2half_rn(v - __half2float(h));
    g_Wt_hi[n * FDIM + k] = h;
    g_Wt_lo[n * FDIM + k] = l;
}

// ======= GEMM via mma.sync, A in fp16 (hi only), B fp16 hi/lo split =======
// H = X(N,128) @ W(128,128). 128-row tile per block, 256 threads.
// 3 smem buffers (104KB) -> 2 blocks/SM. Fused attn-scalar epilogue.
#define SA 136                    // smem row stride in halfs (conflict-free)
#define GSM_BYTES (3 * 128 * SA * 2)   // Ahi, Bhi, Blo = 104448 B

__device__ __forceinline__ void mma16816(float* c, uint32_t a0, uint32_t a1,
                                         uint32_t a2, uint32_t a3,
                                         uint32_t b0, uint32_t b1) {
    asm volatile(
        "mma.sync.aligned.m16n8k16.row.col.f32.f16.f16.f32 "
        "{%0,%1,%2,%3}, {%4,%5,%6,%7}, {%8,%9}, {%0,%1,%2,%3};"
        : "+f"(c[0]), "+f"(c[1]), "+f"(c[2]), "+f"(c[3])
        : "r"(a0), "r"(a1), "r"(a2), "r"(a3), "r"(b0), "r"(b1));
}

__global__ void __launch_bounds__(256) gemm_mma(const float* __restrict__ Xext,
                                                int xsel,
                                                const float* __restrict__ a_s,
                                                const float* __restrict__ a_d) {
    extern __shared__ __align__(16) __half smh[];
    __half* Ahi = smh;
    __half* Bhi = Ahi + 128 * SA;
    __half* Blo = Bhi + 128 * SA;
    __shared__ float as_s[128], ad_s[128];

    const float* X = sel_x(Xext, xsel);
    const int tid  = threadIdx.x;
    const int lane = tid & 31;
    const int wid  = tid >> 5;
    const int g    = lane >> 2;       // 0..7
    const int c    = lane & 3;        // 0..3
    const int row0 = blockIdx.x * 128;
    const int arow = wid * 16 + g;    // fragment row within tile

    if (tid < 128) { as_s[tid] = a_s[tid]; ad_s[tid] = a_d[tid]; }

    // ---- fill A tile (X fp32 -> fp16) ----
    for (int it = tid; it < 128 * 32; it += 256) {
        int r = it >> 5, j = it & 31;          // j: float4 col
        float4 v = make_float4(0.f, 0.f, 0.f, 0.f);
        if (row0 + r < NN)
            v = reinterpret_cast<const float4*>(X)[(row0 + r) * 32 + j];
        __half2 h01 = __floats2half2_rn(v.x, v.y);
        __half2 h23 = __floats2half2_rn(v.z, v.w);
        uint2 hv = make_uint2(*(uint32_t*)&h01, *(uint32_t*)&h23);
        *reinterpret_cast<uint2*>(&Ahi[r * SA + 4 * j]) = hv;
    }
    // ---- fill B tiles from preconverted g_Wt ([n][k] fp16) ----
    for (int it = tid; it < 128 * 16; it += 256) {
        int n = it >> 4, j = it & 15;          // j: 8-half chunk
        *reinterpret_cast<uint4*>(&Bhi[n * SA + 8 * j]) =
            reinterpret_cast<const uint4*>(g_Wt_hi)[n * 16 + j];
        *reinterpret_cast<uint4*>(&Blo[n * SA + 8 * j]) =
            reinterpret_cast<const uint4*>(g_Wt_lo)[n * 16 + j];
    }
    __syncthreads();

    // ---- mainloop ----
    float acc[16][4];
#pragma unroll
    for (int nt = 0; nt < 16; nt++)
#pragma unroll
        for (int q = 0; q < 4; q++) acc[nt][q] = 0.f;

#pragma unroll
    for (int ks = 0; ks < 8; ks++) {
        const int kb = ks * 16 + 2 * c;
        uint32_t ah0 = *(uint32_t*)&Ahi[arow * SA + kb];
        uint32_t ah1 = *(uint32_t*)&Ahi[(arow + 8) * SA + kb];
        uint32_t ah2 = *(uint32_t*)&Ahi[arow * SA + kb + 8];
        uint32_t ah3 = *(uint32_t*)&Ahi[(arow + 8) * SA + kb + 8];
#pragma unroll
        for (int nt = 0; nt < 16; nt++) {
            const int nrow = nt * 8 + g;
            uint32_t bh0 = *(uint32_t*)&Bhi[nrow * SA + kb];
            uint32_t bh1 = *(uint32_t*)&Bhi[nrow * SA + kb + 8];
            uint32_t bl0 = *(uint32_t*)&Blo[nrow * SA + kb];
            uint32_t bl1 = *(uint32_t*)&Blo[nrow * SA + kb + 8];
            mma16816(acc[nt], ah0, ah1, ah2, ah3, bh0, bh1);
            mma16816(acc[nt], ah0, ah1, ah2, ah3, bl0, bl1);
        }
    }

    // ---- epilogue: attn scalars from accumulators + fp16 H store ----
    float ps[2][4], pd[2][4];
#pragma unroll
    for (int r2 = 0; r2 < 2; r2++)
#pragma unroll
        for (int h = 0; h < 4; h++) { ps[r2][h] = 0.f; pd[r2][h] = 0.f; }

#pragma unroll
    for (int nt = 0; nt < 16; nt++) {
        const int head = nt >> 2;
        const int col = nt * 8 + 2 * c;
        float s0 = as_s[col], s1 = as_s[col + 1];
        float d0 = ad_s[col], d1 = ad_s[col + 1];
        ps[0][head] += acc[nt][0] * s0 + acc[nt][1] * s1;
        pd[0][head] += acc[nt][0] * d0 + acc[nt][1] * d1;
        ps[1][head] += acc[nt][2] * s0 + acc[nt][3] * s1;
        pd[1][head] += acc[nt][2] * d0 + acc[nt][3] * d1;
    }
#pragma unroll
    for (int off = 1; off <= 2; off <<= 1)
#pragma unroll
        for (int r2 = 0; r2 < 2; r2++)
#pragma unroll
            for (int h = 0; h < 4; h++) {
                ps[r2][h] += __shfl_xor_sync(0xffffffffu, ps[r2][h], off);
                pd[r2][h] += __shfl_xor_sync(0xffffffffu, pd[r2][h], off);
            }
    if (c == 0) {
        int rA = row0 + arow, rB = rA + 8;
        if (rA < NN) {
            reinterpret_cast<float4*>(g_asrc)[rA] =
                make_float4(ps[0][0], ps[0][1], ps[0][2], ps[0][3]);
            reinterpret_cast<float4*>(g_adst)[rA] =
                make_float4(pd[0][0], pd[0][1], pd[0][2], pd[0][3]);
        }
        if (rB < NN) {
            reinterpret_cast<float4*>(g_asrc)[rB] =
                make_float4(ps[1][0], ps[1][1], ps[1][2], ps[1][3]);
            reinterpret_cast<float4*>(g_adst)[rB] =
                make_float4(pd[1][0], pd[1][1], pd[1][2], pd[1][3]);
        }
    }

    {
        int rA = row0 + arow, rB = rA + 8;
#pragma unroll
        for (int nt = 0; nt < 16; nt++) {
            const int col = nt * 8 + 2 * c;
            if (rA < NN) {
                __half2 v = __floats2half2_rn(acc[nt][0], acc[nt][1]);
                *reinterpret_cast<uint32_t*>(&g_Hh[rA * 128 + col]) =
                    *reinterpret_cast<uint32_t*>(&v);
            }
            if (rB < NN) {
                __half2 v = __floats2half2_rn(acc[nt][2], acc[nt][3]);
                *reinterpret_cast<uint32_t*>(&g_Hh[rB * 128 + col]) =
                    *reinterpret_cast<uint32_t*>(&v);
            }
        }
    }
}

// ======= fused softmax + aggregate: SINGLE PASS, one warp per dst node =======
// Denominator factorizes: out = (sum_j x_j * h_j) / (sum_j x_j). Per 32-edge
// chunk, each lane holds one edge's csr index + 4 head exp's in REGISTERS;
// the half-warp inner loop reads them via shfl (no g_ex array, no 2nd CSR
// sweep, no threadfence). Normalize once at the end.
__global__ void __launch_bounds__(256) fused_edge(int aggsel,
                                                  const float* __restrict__ b) {
    int gw   = (blockIdx.x * blockDim.x + threadIdx.x) >> 5;
    int lane = threadIdx.x & 31;
    if (gw >= NN) return;
    const int d   = gw;
    const int beg = g_off[d];
    const int end = g_off[d + 1];   // >= beg+1 (self loop)

    float4 ad4 = reinterpret_cast<const float4*>(g_adst)[d];

    const int half = lane >> 4;   // 0: even edge, 1: odd edge
    const int fl   = lane & 15;   // feature group [8*fl, 8*fl+8)
    const int hl   = fl >> 2;     // head of this feature group

    float s0 = 0.f, s1 = 0.f, s2 = 0.f, s3 = 0.f;   // denom accum (lane-strided)
    float a8[8];
#pragma unroll
    for (int j = 0; j < 8; j++) a8[j] = 0.f;

    for (int i0 = beg; i0 < end; i0 += 32) {
        int i = i0 + lane;
        bool valid = i < end;
        int s_r = valid ? g_csr_src[i] : 0;
        float4 as = reinterpret_cast<const float4*>(g_asrc)[s_r];
        float x0 = valid ? __expf(fminf(lrelu(as.x + ad4.x), 30.f)) : 0.f;
        float x1 = valid ? __expf(fminf(lrelu(as.y + ad4.y), 30.f)) : 0.f;
        float x2 = valid ? __expf(fminf(lrelu(as.z + ad4.z), 30.f)) : 0.f;
        float x3 = valid ? __expf(fminf(lrelu(as.w + ad4.w), 30.f)) : 0.f;
        s0 += x0; s1 += x1; s2 += x2; s3 += x3;

        int cnt = min(32, end - i0);
#pragma unroll 4
        for (int j = 0; j < cnt; j += 2) {
            int jj = j + half;                 // may be == cnt (odd cnt, half=1)
            int s = __shfl_sync(0xffffffffu, s_r, jj);      // 0 if jj invalid
            float v0 = __shfl_sync(0xffffffffu, x0, jj);
            float v1 = __shfl_sync(0xffffffffu, x1, jj);
            float v2 = __shfl_sync(0xffffffffu, x2, jj);
            float v3 = __shfl_sync(0xffffffffu, x3, jj);
            float xh = (hl & 2) ? ((hl & 1) ? v3 : v2)
                                : ((hl & 1) ? v1 : v0);
            float a = (jj < cnt) ? xh : 0.f;   // invalid edge contributes 0
            uint4 hv = reinterpret_cast<const uint4*>(g_Hh)[s * 16 + fl];
            float2 f0 = __half22float2(*reinterpret_cast<__half2*>(&hv.x));
            float2 f1 = __half22float2(*reinterpret_cast<__half2*>(&hv.y));
            float2 f2 = __half22float2(*reinterpret_cast<__half2*>(&hv.z));
            float2 f3 = __half22float2(*reinterpret_cast<__half2*>(&hv.w));
            a8[0] += a * f0.x; a8[1] += a * f0.y;
            a8[2] += a * f1.x; a8[3] += a * f1.y;
            a8[4] += a * f2.x; a8[5] += a * f2.y;
            a8[6] += a * f3.x; a8[7] += a * f3.y;
        }
    }

    // reduce denominators across the warp
#pragma unroll
    for (int off = 16; off > 0; off >>= 1) {
        s0 += __shfl_xor_sync(0xffffffffu, s0, off);
        s1 += __shfl_xor_sync(0xffffffffu, s1, off);
        s2 += __shfl_xor_sync(0xffffffffu, s2, off);
        s3 += __shfl_xor_sync(0xffffffffu, s3, off);
    }
    float sh = (hl & 2) ? ((hl & 1) ? s3 : s2) : ((hl & 1) ? s1 : s0);
    float rh = 1.f / (sh + 1e-16f);

    // combine the two half-warps, then normalize + bias + relu + store
#pragma unroll
    for (int j = 0; j < 8; j++)
        a8[j] += __shfl_xor_sync(0xffffffffu, a8[j], 16);

    if (half == 0) {
        const float4* b4 = reinterpret_cast<const float4*>(b);
        float4 b0 = b4[fl * 2], b1 = b4[fl * 2 + 1];
        float4 o0, o1;
        o0.x = fmaxf(a8[0] * rh + b0.x, 0.f);
        o0.y = fmaxf(a8[1] * rh + b0.y, 0.f);
        o0.z = fmaxf(a8[2] * rh + b0.z, 0.f);
        o0.w = fmaxf(a8[3] * rh + b0.w, 0.f);
        o1.x = fmaxf(a8[4] * rh + b1.x, 0.f);
        o1.y = fmaxf(a8[5] * rh + b1.y, 0.f);
        o1.z = fmaxf(a8[6] * rh + b1.z, 0.f);
        o1.w = fmaxf(a8[7] * rh + b1.w, 0.f);
        float4* outp =
            reinterpret_cast<float4*>(sel_buf(aggsel) + d * 128 + fl * 8);
        outp[0] = o0;
        outp[1] = o1;
    }
}

// ---------------- mean pool per graph (batch is sorted int32) ----------------
__device__ __forceinline__ int lbound_i(const int* a, int n, int v) {
    int lo = 0, hi = n;
    while (lo < hi) {
        int mid = (lo + hi) >> 1;
        if (a[mid] < v) lo = mid + 1; else hi = mid;
    }
    return lo;
}

__global__ void pool_kernel(const int* __restrict__ batch, int sel) {
    __shared__ int se[2];
    __shared__ float s[128];
    int g = blockIdx.x;
    int t = threadIdx.x;
    if (t == 0) {
        se[0] = lbound_i(batch, NN, g);
        se[1] = lbound_i(batch, NN, g + 1);
    }
    __syncthreads();
    int start = se[0], end = se[1];
    const float* h = sel_buf(sel);
    int f = t & 127;
    float acc = 0.f;
    for (int n = start + (t >> 7); n < end; n += 2)
        acc += h[n * 128 + f];
    if (t < 128) s[t] = acc;
    __syncthreads();
    if (t >= 128) s[f] += acc;   // exactly one writer per f
    __syncthreads();
    if (t < 128)
        g_pooled[g * 128 + t] = s[t] / fmaxf((float)(end - start), 1.0f);
}

// ---------------- final FC: [64,128] @ [128,10] + b ----------------
__global__ void fc_kernel(const float* __restrict__ fcW,
                          const float* __restrict__ fcb,
                          float* __restrict__ out) {
    int t = threadIdx.x;
    if (t >= NGRAPH * OUTCH) return;
    int g = t / OUTCH, o = t % OUTCH;
    float acc = fcb[o];
#pragma unroll 8
    for (int k = 0; k < 128; k++)
        acc += g_pooled[g * 128 + k] * fcW[k * OUTCH + o];
    out[t] = acc;
}

// ---------------- driver ----------------
static void run_layer(const float* x_ext, int xsel, int aggsel,
                      const float* W, const float* a_s, const float* a_d,
                      const float* b) {
    conv_w<<<(FDIM * FDIM + 255) / 256, 256>>>(W);
    gemm_mma<<<(NN + 127) / 128, 256, GSM_BYTES>>>(x_ext, xsel, a_s, a_d);
    fused_edge<<<(NN + 7) / 8, 256>>>(aggsel, b);
}

extern "C" void kernel_launch(void* const* d_in, const int* in_sizes, int n_in,
                              void* d_out, int out_size) {
    const float* x     = (const float*)d_in[0];
    const int*   ei    = (const int*)d_in[1];    // int32 (JAX x64 disabled)
    const int*   batch = (const int*)d_in[2];
    const float* W1  = (const float*)d_in[3];
    const float* a1s = (const float*)d_in[4];
    const float* a1d = (const float*)d_in[5];
    const float* b1  = (const float*)d_in[6];
    const float* W2  = (const float*)d_in[7];
    const float* a2s = (const float*)d_in[8];
    const float* a2d = (const float*)d_in[9];
    const float* b2  = (const float*)d_in[10];
    const float* W3  = (const float*)d_in[11];
    const float* a3s = (const float*)d_in[12];
    const float* a3d = (const float*)d_in[13];
    const float* b3  = (const float*)d_in[14];
    const float* fcW = (const float*)d_in[15];
    const float* fcb = (const float*)d_in[16];

    cudaFuncSetAttribute(gemm_mma, cudaFuncAttributeMaxDynamicSharedMemorySize,
                         GSM_BYTES);

    int E = in_sizes[1] / 2;
    int total = E + NN;
    const int* srcs = ei;
    const int* dsts = ei + E;

    // CSR build (graph static across layers)
    init_deg<<<(NN + 255) / 256, 256>>>();
    count_deg<<<(E + 255) / 256, 256>>>(dsts, E);
    scan_deg<<<1, 1024>>>();
    scatter_edges<<<(total + 255) / 256, 256>>>(srcs, dsts, E, total);

    // layer 1: x -> P,  layer 2: P -> Q,  layer 3: Q -> P
    run_layer(x,       0, 1, W1, a1s, a1d, b1);
    run_layer(nullptr, 1, 2, W2, a2s, a2d, b2);
    run_layer(nullptr, 2, 1, W3, a3s, a3d, b3);

    pool_kernel<<<NGRAPH, 256>>>(batch, 1);
    fc_kernel<<<1, NGRAPH * OUTCH>>>(fcW, fcb, (float*)d_out);
}

// round 14
// speedup vs baseline: 1.1404x; 1.1404x over previous
#include <cuda_runtime.h>
#include <cuda_bf16.h>
#include <cuda_fp16.h>
#include <cstdint>

// Problem constants (fixed by the dataset)
#define NN      50000
#define FDIM    128
#define HEADS   4
#define NGRAPH  64
#define OUTCH   10
#define NEG     0.2f
#define MAXE    800000
#define MAXTOT  (MAXE + NN)   // edges + self loops

// ---------------- device scratch (static, no allocation) ----------------
__device__ __align__(16) __half g_Hh[NN * FDIM];   // gemm output (pre-bias h), fp16
__device__ __align__(16) float  g_P[NN * FDIM];    // ping buffer
__device__ __align__(16) float  g_Q[NN * FDIM];    // pong buffer
__device__ __align__(16) float  g_asrc[NN * HEADS];
__device__ __align__(16) float  g_adst[NN * HEADS];
__device__ __align__(16) float  g_ex[MAXTOT * HEADS]; // exp(e) per edge per head
__device__ __align__(16) float  g_pooled[NGRAPH * FDIM];
// W split into fp16 hi/lo, transposed to [n][k]; all 3 layers converted once
__device__ __align__(16) __half g_Wt_hi[3][FDIM * FDIM];
__device__ __align__(16) __half g_Wt_lo[3][FDIM * FDIM];
// CSR by destination (built once per launch; graph static across layers)
__device__ int g_deg[NN];
__device__ int g_off[NN + 1];
__device__ int g_cursor[NN];
__device__ int g_csr_src[MAXTOT];

__device__ __forceinline__ float lrelu(float e) { return e > 0.f ? e : NEG * e; }

__device__ __forceinline__ float* sel_buf(int sel) {
    return sel == 1 ? g_P : g_Q;
}
__device__ __forceinline__ const float* sel_x(const float* ext, int sel) {
    return sel == 0 ? ext : (sel == 1 ? g_P : g_Q);
}

// ================= CSR build (once per launch) =================
__global__ void init_deg() {
    int i = blockIdx.x * blockDim.x + threadIdx.x;
    if (i < NN) g_deg[i] = 1;          // self loop
}
// 4 edges per thread, int4 loads, independent atomics (MLP x4)
__global__ void count_deg4(const int* __restrict__ dsts, int E) {
    int t = blockIdx.x * blockDim.x + threadIdx.x;
    int i0 = t * 4;
    if (i0 + 3 < E) {
        int4 d4 = reinterpret_cast<const int4*>(dsts)[t];
        atomicAdd(&g_deg[d4.x], 1);
        atomicAdd(&g_deg[d4.y], 1);
        atomicAdd(&g_deg[d4.z], 1);
        atomicAdd(&g_deg[d4.w], 1);
    } else {
        for (int i = i0; i < E; i++) atomicAdd(&g_deg[dsts[i]], 1);
    }
}
// one block, 1024 threads: chunked exclusive scan of g_deg -> g_off, g_cursor
__global__ void scan_deg() {
    __shared__ int part[1024];
    const int CH = (NN + 1023) / 1024;   // 49
    int t = threadIdx.x;
    int base = t * CH;
    int s = 0;
    for (int k = 0; k < CH; k++) {
        int idx = base + k;
        if (idx < NN) s += g_deg[idx];
    }
    part[t] = s;
    __syncthreads();
    for (int off = 1; off < 1024; off <<= 1) {
        int v = (t >= off) ? part[t - off] : 0;
        __syncthreads();
        part[t] += v;
        __syncthreads();
    }
    int run = part[t] - s;     // exclusive start of this chunk
    for (int k = 0; k < CH; k++) {
        int idx = base + k;
        if (idx < NN) {
            g_off[idx]    = run;
            g_cursor[idx] = run;
            run += g_deg[idx];
        }
    }
    if (t == 0) g_off[NN] = part[1023];
}
// 4 edges per thread (int4 loads); self loops handled by trailing threads
__global__ void scatter_edges4(const int* __restrict__ srcs,
                               const int* __restrict__ dsts, int E, int nq) {
    int t = blockIdx.x * blockDim.x + threadIdx.x;
    if (t < nq) {
        int i0 = t * 4;
        if (i0 + 3 < E) {
            int4 s4 = reinterpret_cast<const int4*>(srcs)[t];
            int4 d4 = reinterpret_cast<const int4*>(dsts)[t];
            g_csr_src[atomicAdd(&g_cursor[d4.x], 1)] = s4.x;
            g_csr_src[atomicAdd(&g_cursor[d4.y], 1)] = s4.y;
            g_csr_src[atomicAdd(&g_cursor[d4.z], 1)] = s4.z;
            g_csr_src[atomicAdd(&g_cursor[d4.w], 1)] = s4.w;
        } else {
            for (int i = i0; i < E; i++)
                g_csr_src[atomicAdd(&g_cursor[dsts[i]], 1)] = srcs[i];
        }
    } else {
        int n = t - nq;                 // self loop for node n
        if (n < NN)
            g_csr_src[atomicAdd(&g_cursor[n], 1)] = n;
    }
}

// ========== all 3 W's -> fp16 hi/lo, transposed [n][k] (one launch) ==========
__global__ void conv_w_all(const float* __restrict__ W1,
                           const float* __restrict__ W2,
                           const float* __restrict__ W3) {
    int t = blockIdx.x * blockDim.x + threadIdx.x;
    if (t >= 3 * FDIM * FDIM) return;
    int l = t / (FDIM * FDIM);
    int i = t - l * (FDIM * FDIM);
    const float* W = l == 0 ? W1 : (l == 1 ? W2 : W3);
    int k = i >> 7, n = i & 127;
    float v = W[i];                       // W[k][n]
    __half h = __float2half_rn(v);
    __half lo = __float2half_rn(v - __half2float(h));
    g_Wt_hi[l][n * FDIM + k] = h;
    g_Wt_lo[l][n * FDIM + k] = lo;
}

// ======= GEMM via mma.sync, A in fp16 (hi only), B fp16 hi/lo split =======
// H = X(N,128) @ W(128,128). 128-row tile per block, 256 threads.
// 3 smem buffers (104KB) -> 2 blocks/SM. Fused attn-scalar epilogue.
#define SA 136                    // smem row stride in halfs (conflict-free)
#define GSM_BYTES (3 * 128 * SA * 2)   // Ahi, Bhi, Blo = 104448 B

__device__ __forceinline__ void mma16816(float* c, uint32_t a0, uint32_t a1,
                                         uint32_t a2, uint32_t a3,
                                         uint32_t b0, uint32_t b1) {
    asm volatile(
        "mma.sync.aligned.m16n8k16.row.col.f32.f16.f16.f32 "
        "{%0,%1,%2,%3}, {%4,%5,%6,%7}, {%8,%9}, {%0,%1,%2,%3};"
        : "+f"(c[0]), "+f"(c[1]), "+f"(c[2]), "+f"(c[3])
        : "r"(a0), "r"(a1), "r"(a2), "r"(a3), "r"(b0), "r"(b1));
}

__global__ void __launch_bounds__(256) gemm_mma(const float* __restrict__ Xext,
                                                int xsel, int layer,
                                                const float* __restrict__ a_s,
                                                const float* __restrict__ a_d) {
    extern __shared__ __align__(16) __half smh[];
    __half* Ahi = smh;
    __half* Bhi = Ahi + 128 * SA;
    __half* Blo = Bhi + 128 * SA;
    __shared__ float as_s[128], ad_s[128];

    const float* X = sel_x(Xext, xsel);
    const int tid  = threadIdx.x;
    const int lane = tid & 31;
    const int wid  = tid >> 5;
    const int g    = lane >> 2;       // 0..7
    const int c    = lane & 3;        // 0..3
    const int row0 = blockIdx.x * 128;
    const int arow = wid * 16 + g;    // fragment row within tile

    if (tid < 128) { as_s[tid] = a_s[tid]; ad_s[tid] = a_d[tid]; }

    // ---- fill A tile (X fp32 -> fp16) ----
    for (int it = tid; it < 128 * 32; it += 256) {
        int r = it >> 5, j = it & 31;          // j: float4 col
        float4 v = make_float4(0.f, 0.f, 0.f, 0.f);
        if (row0 + r < NN)
            v = reinterpret_cast<const float4*>(X)[(row0 + r) * 32 + j];
        __half2 h01 = __floats2half2_rn(v.x, v.y);
        __half2 h23 = __floats2half2_rn(v.z, v.w);
        uint2 hv = make_uint2(*(uint32_t*)&h01, *(uint32_t*)&h23);
        *reinterpret_cast<uint2*>(&Ahi[r * SA + 4 * j]) = hv;
    }
    // ---- fill B tiles from preconverted g_Wt ([n][k] fp16) ----
    {
        const __half* wh = g_Wt_hi[layer];
        const __half* wl = g_Wt_lo[layer];
        for (int it = tid; it < 128 * 16; it += 256) {
            int n = it >> 4, j = it & 15;      // j: 8-half chunk
            *reinterpret_cast<uint4*>(&Bhi[n * SA + 8 * j]) =
                reinterpret_cast<const uint4*>(wh)[n * 16 + j];
            *reinterpret_cast<uint4*>(&Blo[n * SA + 8 * j]) =
                reinterpret_cast<const uint4*>(wl)[n * 16 + j];
        }
    }
    __syncthreads();

    // ---- mainloop ----
    float acc[16][4];
#pragma unroll
    for (int nt = 0; nt < 16; nt++)
#pragma unroll
        for (int q = 0; q < 4; q++) acc[nt][q] = 0.f;

#pragma unroll
    for (int ks = 0; ks < 8; ks++) {
        const int kb = ks * 16 + 2 * c;
        uint32_t ah0 = *(uint32_t*)&Ahi[arow * SA + kb];
        uint32_t ah1 = *(uint32_t*)&Ahi[(arow + 8) * SA + kb];
        uint32_t ah2 = *(uint32_t*)&Ahi[arow * SA + kb + 8];
        uint32_t ah3 = *(uint32_t*)&Ahi[(arow + 8) * SA + kb + 8];
#pragma unroll
        for (int nt = 0; nt < 16; nt++) {
            const int nrow = nt * 8 + g;
            uint32_t bh0 = *(uint32_t*)&Bhi[nrow * SA + kb];
            uint32_t bh1 = *(uint32_t*)&Bhi[nrow * SA + kb + 8];
            uint32_t bl0 = *(uint32_t*)&Blo[nrow * SA + kb];
            uint32_t bl1 = *(uint32_t*)&Blo[nrow * SA + kb + 8];
            mma16816(acc[nt], ah0, ah1, ah2, ah3, bh0, bh1);
            mma16816(acc[nt], ah0, ah1, ah2, ah3, bl0, bl1);
        }
    }

    // ---- epilogue: attn scalars from accumulators + fp16 H store ----
    float ps[2][4], pd[2][4];
#pragma unroll
    for (int r2 = 0; r2 < 2; r2++)
#pragma unroll
        for (int h = 0; h < 4; h++) { ps[r2][h] = 0.f; pd[r2][h] = 0.f; }

#pragma unroll
    for (int nt = 0; nt < 16; nt++) {
        const int head = nt >> 2;
        const int col = nt * 8 + 2 * c;
        float s0 = as_s[col], s1 = as_s[col + 1];
        float d0 = ad_s[col], d1 = ad_s[col + 1];
        ps[0][head] += acc[nt][0] * s0 + acc[nt][1] * s1;
        pd[0][head] += acc[nt][0] * d0 + acc[nt][1] * d1;
        ps[1][head] += acc[nt][2] * s0 + acc[nt][3] * s1;
        pd[1][head] += acc[nt][2] * d0 + acc[nt][3] * d1;
    }
#pragma unroll
    for (int off = 1; off <= 2; off <<= 1)
#pragma unroll
        for (int r2 = 0; r2 < 2; r2++)
#pragma unroll
            for (int h = 0; h < 4; h++) {
                ps[r2][h] += __shfl_xor_sync(0xffffffffu, ps[r2][h], off);
                pd[r2][h] += __shfl_xor_sync(0xffffffffu, pd[r2][h], off);
            }
    if (c == 0) {
        int rA = row0 + arow, rB = rA + 8;
        if (rA < NN) {
            reinterpret_cast<float4*>(g_asrc)[rA] =
                make_float4(ps[0][0], ps[0][1], ps[0][2], ps[0][3]);
            reinterpret_cast<float4*>(g_adst)[rA] =
                make_float4(pd[0][0], pd[0][1], pd[0][2], pd[0][3]);
        }
        if (rB < NN) {
            reinterpret_cast<float4*>(g_asrc)[rB] =
                make_float4(ps[1][0], ps[1][1], ps[1][2], ps[1][3]);
            reinterpret_cast<float4*>(g_adst)[rB] =
                make_float4(pd[1][0], pd[1][1], pd[1][2], pd[1][3]);
        }
    }

    {
        int rA = row0 + arow, rB = rA + 8;
#pragma unroll
        for (int nt = 0; nt < 16; nt++) {
            const int col = nt * 8 + 2 * c;
            if (rA < NN) {
                __half2 v = __floats2half2_rn(acc[nt][0], acc[nt][1]);
                *reinterpret_cast<uint32_t*>(&g_Hh[rA * 128 + col]) =
                    *reinterpret_cast<uint32_t*>(&v);
            }
            if (rB < NN) {
                __half2 v = __floats2half2_rn(acc[nt][2], acc[nt][3]);
                *reinterpret_cast<uint32_t*>(&g_Hh[rB * 128 + col]) =
                    *reinterpret_cast<uint32_t*>(&v);
            }
        }
    }
}

// ======= fused softmax + aggregate: one warp per destination node =======
// (R12 winner, verbatim.) No max pass; exp(e) cached in g_ex. Pass 2:
// half-warp per edge (16 lanes x uint4), 2 edges/iteration, LDG.128 gathers.
__global__ void __launch_bounds__(256) fused_edge(int aggsel,
                                                  const float* __restrict__ b) {
    int gw   = (blockIdx.x * blockDim.x + threadIdx.x) >> 5;
    int lane = threadIdx.x & 31;
    if (gw >= NN) return;
    const int d   = gw;
    const int beg = g_off[d];
    const int end = g_off[d + 1];   // >= beg+1 (self loop)

    float4 ad4 = reinterpret_cast<const float4*>(g_adst)[d];

    // pass 1: exp(e) per edge (cached) + per-head denominator
    float s0 = 0.f, s1 = 0.f, s2 = 0.f, s3 = 0.f;
    for (int i = beg + lane; i < end; i += 32) {
        int s = g_csr_src[i];
        float4 as = reinterpret_cast<const float4*>(g_asrc)[s];
        float x0 = __expf(fminf(lrelu(as.x + ad4.x), 30.f));
        float x1 = __expf(fminf(lrelu(as.y + ad4.y), 30.f));
        float x2 = __expf(fminf(lrelu(as.z + ad4.z), 30.f));
        float x3 = __expf(fminf(lrelu(as.w + ad4.w), 30.f));
        reinterpret_cast<float4*>(g_ex)[i] = make_float4(x0, x1, x2, x3);
        s0 += x0; s1 += x1; s2 += x2; s3 += x3;
    }
#pragma unroll
    for (int off = 16; off > 0; off >>= 1) {
        s0 += __shfl_xor_sync(0xffffffffu, s0, off);
        s1 += __shfl_xor_sync(0xffffffffu, s1, off);
        s2 += __shfl_xor_sync(0xffffffffu, s2, off);
        s3 += __shfl_xor_sync(0xffffffffu, s3, off);
    }

    __threadfence_block();   // make this warp's g_ex stores visible to all lanes
    __syncwarp();

    const int half = lane >> 4;   // 0: edge i, 1: edge i+1
    const int fl   = lane & 15;   // feature group [8*fl, 8*fl+8)
    const int hl   = fl >> 2;     // head of this feature group
    float sh = (hl & 2) ? ((hl & 1) ? s3 : s2) : ((hl & 1) ? s1 : s0);
    float rh = 1.f / (sh + 1e-16f);

    float a8[8];
#pragma unroll
    for (int j = 0; j < 8; j++) a8[j] = 0.f;

    int i = beg;
#pragma unroll 2
    for (; i + 1 < end; i += 2) {
        int idx = i + half;
        int s = g_csr_src[idx];
        float a = g_ex[idx * 4 + hl] * rh;
        uint4 hv = reinterpret_cast<const uint4*>(g_Hh)[s * 16 + fl];
        float2 f0 = __half22float2(*reinterpret_cast<__half2*>(&hv.x));
        float2 f1 = __half22float2(*reinterpret_cast<__half2*>(&hv.y));
        float2 f2 = __half22float2(*reinterpret_cast<__half2*>(&hv.z));
        float2 f3 = __half22float2(*reinterpret_cast<__half2*>(&hv.w));
        a8[0] += a * f0.x; a8[1] += a * f0.y;
        a8[2] += a * f1.x; a8[3] += a * f1.y;
        a8[4] += a * f2.x; a8[5] += a * f2.y;
        a8[6] += a * f3.x; a8[7] += a * f3.y;
    }
    if (i < end) {                  // leftover edge: only half 0 contributes
        int s = g_csr_src[i];
        float a = (half == 0) ? g_ex[i * 4 + hl] * rh : 0.f;
        uint4 hv = reinterpret_cast<const uint4*>(g_Hh)[s * 16 + fl];
        float2 f0 = __half22float2(*reinterpret_cast<__half2*>(&hv.x));
        float2 f1 = __half22float2(*reinterpret_cast<__half2*>(&hv.y));
        float2 f2 = __half22float2(*reinterpret_cast<__half2*>(&hv.z));
        float2 f3 = __half22float2(*reinterpret_cast<__half2*>(&hv.w));
        a8[0] += a * f0.x; a8[1] += a * f0.y;
        a8[2] += a * f1.x; a8[3] += a * f1.y;
        a8[4] += a * f2.x; a8[5] += a * f2.y;
        a8[6] += a * f3.x; a8[7] += a * f3.y;
    }
    // combine the two half-warps
#pragma unroll
    for (int j = 0; j < 8; j++)
        a8[j] += __shfl_xor_sync(0xffffffffu, a8[j], 16);

    if (half == 0) {
        const float4* b4 = reinterpret_cast<const float4*>(b);
        float4 b0 = b4[fl * 2], b1 = b4[fl * 2 + 1];
        float4 o0, o1;
        o0.x = fmaxf(a8[0] + b0.x, 0.f);
        o0.y = fmaxf(a8[1] + b0.y, 0.f);
        o0.z = fmaxf(a8[2] + b0.z, 0.f);
        o0.w = fmaxf(a8[3] + b0.w, 0.f);
        o1.x = fmaxf(a8[4] + b1.x, 0.f);
        o1.y = fmaxf(a8[5] + b1.y, 0.f);
        o1.z = fmaxf(a8[6] + b1.z, 0.f);
        o1.w = fmaxf(a8[7] + b1.w, 0.f);
        float4* outp =
            reinterpret_cast<float4*>(sel_buf(aggsel) + d * 128 + fl * 8);
        outp[0] = o0;
        outp[1] = o1;
    }
}

// ---------------- mean pool per graph (batch is sorted int32) ----------------
__device__ __forceinline__ int lbound_i(const int* a, int n, int v) {
    int lo = 0, hi = n;
    while (lo < hi) {
        int mid = (lo + hi) >> 1;
        if (a[mid] < v) lo = mid + 1; else hi = mid;
    }
    return lo;
}

__global__ void pool_kernel(const int* __restrict__ batch, int sel) {
    __shared__ int se[2];
    __shared__ float s[128];
    int g = blockIdx.x;
    int t = threadIdx.x;
    if (t == 0) {
        se[0] = lbound_i(batch, NN, g);
        se[1] = lbound_i(batch, NN, g + 1);
    }
    __syncthreads();
    int start = se[0], end = se[1];
    const float* h = sel_buf(sel);
    int f = t & 127;
    float acc = 0.f;
    for (int n = start + (t >> 7); n < end; n += 2)
        acc += h[n * 128 + f];
    if (t < 128) s[t] = acc;
    __syncthreads();
    if (t >= 128) s[f] += acc;   // exactly one writer per f
    __syncthreads();
    if (t < 128)
        g_pooled[g * 128 + t] = s[t] / fmaxf((float)(end - start), 1.0f);
}

// ---------------- final FC: [64,128] @ [128,10] + b ----------------
__global__ void fc_kernel(const float* __restrict__ fcW,
                          const float* __restrict__ fcb,
                          float* __restrict__ out) {
    int t = threadIdx.x;
    if (t >= NGRAPH * OUTCH) return;
    int g = t / OUTCH, o = t % OUTCH;
    float acc = fcb[o];
#pragma unroll 8
    for (int k = 0; k < 128; k++)
        acc += g_pooled[g * 128 + k] * fcW[k * OUTCH + o];
    out[t] = acc;
}

// ---------------- driver ----------------
static void run_layer(const float* x_ext, int xsel, int aggsel, int layer,
                      const float* a_s, const float* a_d, const float* b) {
    gemm_mma<<<(NN + 127) / 128, 256, GSM_BYTES>>>(x_ext, xsel, layer, a_s, a_d);
    fused_edge<<<(NN + 7) / 8, 256>>>(aggsel, b);
}

extern "C" void kernel_launch(void* const* d_in, const int* in_sizes, int n_in,
                              void* d_out, int out_size) {
    const float* x     = (const float*)d_in[0];
    const int*   ei    = (const int*)d_in[1];    // int32 (JAX x64 disabled)
    const int*   batch = (const int*)d_in[2];
    const float* W1  = (const float*)d_in[3];
    const float* a1s = (const float*)d_in[4];
    const float* a1d = (const float*)d_in[5];
    const float* b1  = (const float*)d_in[6];
    const float* W2  = (const float*)d_in[7];
    const float* a2s = (const float*)d_in[8];
    const float* a2d = (const float*)d_in[9];
    const float* b2  = (const float*)d_in[10];
    const float* W3  = (const float*)d_in[11];
    const float* a3s = (const float*)d_in[12];
    const float* a3d = (const float*)d_in[13];
    const float* b3  = (const float*)d_in[14];
    const float* fcW = (const float*)d_in[15];
    const float* fcb = (const float*)d_in[16];

    cudaFuncSetAttribute(gemm_mma, cudaFuncAttributeMaxDynamicSharedMemorySize,
                         GSM_BYTES);

    int E = in_sizes[1] / 2;
    const int* srcs = ei;
    const int* dsts = ei + E;
    int nq = (E + 3) / 4;                 // 4-edge work items
    int scat_T = nq + NN;                 // + self loops

    // W conversion (all 3 layers) + CSR build
    conv_w_all<<<(3 * FDIM * FDIM + 255) / 256, 256>>>(W1, W2, W3);
    init_deg<<<(NN + 255) / 256, 256>>>();
    count_deg4<<<(nq + 255) / 256, 256>>>(dsts, E);
    scan_deg<<<1, 1024>>>();
    scatter_edges4<<<(scat_T + 255) / 256, 256>>>(srcs, dsts, E, nq);

    // layer 1: x -> P,  layer 2: P -> Q,  layer 3: Q -> P
    run_layer(x,       0, 1, 0, a1s, a1d, b1);
    run_layer(nullptr, 1, 2, 1, a2s, a2d, b2);
    run_layer(nullptr, 2, 1, 2, a3s, a3d, b3);

    pool_kernel<<<NGRAPH, 256>>>(batch, 1);
    fc_kernel<<<1, NGRAPH * OUTCH>>>(fcW, fcb, (float*)d_out);
}

// round 17
// speedup vs baseline: 1.4816x; 1.2992x over previous
#include <cuda_runtime.h>
#include <cuda_bf16.h>
#include <cuda_fp16.h>
#include <cstdint>

// Problem constants (fixed by the dataset)
#define NN      50000
#define FDIM    128
#define HEADS   4
#define NGRAPH  64
#define OUTCH   10
#define NEG     0.2f
#define MAXE    800000
#define MAXTOT  (MAXE + NN)   // edges + self loops

// ---------------- device scratch (static, no allocation) ----------------
__device__ __align__(16) __half g_Hh[NN * FDIM];   // gemm output (pre-bias h), fp16
__device__ __align__(16) float  g_P[NN * FDIM];    // ping buffer
__device__ __align__(16) float  g_Q[NN * FDIM];    // pong buffer
__device__ __align__(16) float  g_asrc[NN * HEADS];
__device__ __align__(16) float  g_adst[NN * HEADS];
__device__ __align__(16) float  g_ex[MAXTOT * HEADS]; // exp(e) per edge per head
__device__ __align__(16) float  g_pooled[NGRAPH * FDIM];
// W split into fp16 hi/lo, transposed to [n][k]; all 3 layers converted once
__device__ __align__(16) __half g_Wt_hi[3][FDIM * FDIM];
__device__ __align__(16) __half g_Wt_lo[3][FDIM * FDIM];
// CSR by destination (built once per launch; graph static across layers)
__device__ int g_deg[NN];
__device__ int g_off[NN + 1];
__device__ int g_cursor[NN];
__device__ int g_csr_src[MAXTOT];

// multi-block scan scratch
#define SCB  512
#define NSCB ((NN + SCB - 1) / SCB)   // 98
__device__ int g_bsum[NSCB];
__device__ int g_boff[NSCB];

__device__ __forceinline__ float lrelu(float e) { return e > 0.f ? e : NEG * e; }

__device__ __forceinline__ float* sel_buf(int sel) {
    return sel == 1 ? g_P : g_Q;
}
__device__ __forceinline__ const float* sel_x(const float* ext, int sel) {
    return sel == 0 ? ext : (sel == 1 ? g_P : g_Q);
}

// ================= CSR build (once per launch) =================
__global__ void init_deg() {
    int i = blockIdx.x * blockDim.x + threadIdx.x;
    if (i < NN) g_deg[i] = 1;          // self loop
}
// 4 edges per thread, int4 loads, independent atomics (MLP x4)
__global__ void count_deg4(const int* __restrict__ dsts, int E) {
    int t = blockIdx.x * blockDim.x + threadIdx.x;
    int i0 = t * 4;
    if (i0 + 3 < E) {
        int4 d4 = reinterpret_cast<const int4*>(dsts)[t];
        atomicAdd(&g_deg[d4.x], 1);
        atomicAdd(&g_deg[d4.y], 1);
        atomicAdd(&g_deg[d4.z], 1);
        atomicAdd(&g_deg[d4.w], 1);
    } else {
        for (int i = i0; i < E; i++) atomicAdd(&g_deg[dsts[i]], 1);
    }
}
// ---- 3-phase grid-wide exclusive scan of g_deg -> g_off, g_cursor ----
__global__ void scan_p1() {            // grid NSCB, block SCB: block sums
    __shared__ int sh[SCB];
    int t = threadIdx.x;
    int i = blockIdx.x * SCB + t;
    sh[t] = (i < NN) ? g_deg[i] : 0;
    __syncthreads();
    for (int off = SCB / 2; off > 0; off >>= 1) {
        if (t < off) sh[t] += sh[t + off];
        __syncthreads();
    }
    if (t == 0) g_bsum[blockIdx.x] = sh[0];
}
__global__ void scan_p2() {            // 1 block, 128 threads: scan partials
    __shared__ int sh[128];
    int t = threadIdx.x;
    int v = (t < NSCB) ? g_bsum[t] : 0;
    sh[t] = v;
    __syncthreads();
    for (int off = 1; off < 128; off <<= 1) {
        int u = (t >= off) ? sh[t - off] : 0;
        __syncthreads();
        sh[t] += u;
        __syncthreads();
    }
    if (t < NSCB) g_boff[t] = sh[t] - v;   // exclusive block offset
}
__global__ void scan_p3() {            // grid NSCB, block SCB: final scan
    __shared__ int sh[SCB];
    int t = threadIdx.x;
    int i = blockIdx.x * SCB + t;
    int v = (i < NN) ? g_deg[i] : 0;
    sh[t] = v;
    __syncthreads();
    for (int off = 1; off < SCB; off <<= 1) {
        int u = (t >= off) ? sh[t - off] : 0;
        __syncthreads();
        sh[t] += u;
        __syncthreads();
    }
    if (i < NN) {
        int excl = g_boff[blockIdx.x] + sh[t] - v;
        g_off[i]    = excl;
        g_cursor[i] = excl;
        if (i == NN - 1) g_off[NN] = excl + v;
    }
}
// 4 edges per thread (int4 loads); self loops handled by trailing threads
__global__ void scatter_edges4(const int* __restrict__ srcs,
                               const int* __restrict__ dsts, int E, int nq) {
    int t = blockIdx.x * blockDim.x + threadIdx.x;
    if (t < nq) {
        int i0 = t * 4;
        if (i0 + 3 < E) {
            int4 s4 = reinterpret_cast<const int4*>(srcs)[t];
            int4 d4 = reinterpret_cast<const int4*>(dsts)[t];
            g_csr_src[atomicAdd(&g_cursor[d4.x], 1)] = s4.x;
            g_csr_src[atomicAdd(&g_cursor[d4.y], 1)] = s4.y;
            g_csr_src[atomicAdd(&g_cursor[d4.z], 1)] = s4.z;
            g_csr_src[atomicAdd(&g_cursor[d4.w], 1)] = s4.w;
        } else {
            for (int i = i0; i < E; i++)
                g_csr_src[atomicAdd(&g_cursor[dsts[i]], 1)] = srcs[i];
        }
    } else {
        int n = t - nq;                 // self loop for node n
        if (n < NN)
            g_csr_src[atomicAdd(&g_cursor[n], 1)] = n;
    }
}

// ========== all 3 W's -> fp16 hi/lo, transposed [n][k] (one launch) ==========
__global__ void conv_w_all(const float* __restrict__ W1,
                           const float* __restrict__ W2,
                           const float* __restrict__ W3) {
    int t = blockIdx.x * blockDim.x + threadIdx.x;
    if (t >= 3 * FDIM * FDIM) return;
    int l = t / (FDIM * FDIM);
    int i = t - l * (FDIM * FDIM);
    const float* W = l == 0 ? W1 : (l == 1 ? W2 : W3);
    int k = i >> 7, n = i & 127;
    float v = W[i];                       // W[k][n]
    __half h = __float2half_rn(v);
    __half lo = __float2half_rn(v - __half2float(h));
    g_Wt_hi[l][n * FDIM + k] = h;
    g_Wt_lo[l][n * FDIM + k] = lo;
}

// ======= GEMM via mma.sync, A in fp16 (hi only), B fp16 hi/lo split =======
// H = X(N,128) @ W(128,128). 128-row tile per block, 256 threads.
// 3 smem buffers (104KB) -> 2 blocks/SM. Fused attn-scalar epilogue.
#define SA 136                    // smem row stride in halfs (conflict-free)
#define GSM_BYTES (3 * 128 * SA * 2)   // Ahi, Bhi, Blo = 104448 B

__device__ __forceinline__ void mma16816(float* c, uint32_t a0, uint32_t a1,
                                         uint32_t a2, uint32_t a3,
                                         uint32_t b0, uint32_t b1) {
    asm volatile(
        "mma.sync.aligned.m16n8k16.row.col.f32.f16.f16.f32 "
        "{%0,%1,%2,%3}, {%4,%5,%6,%7}, {%8,%9}, {%0,%1,%2,%3};"
        : "+f"(c[0]), "+f"(c[1]), "+f"(c[2]), "+f"(c[3])
        : "r"(a0), "r"(a1), "r"(a2), "r"(a3), "r"(b0), "r"(b1));
}

__global__ void __launch_bounds__(256) gemm_mma(const float* __restrict__ Xext,
                                                int xsel, int layer,
                                                const float* __restrict__ a_s,
                                                const float* __restrict__ a_d) {
    extern __shared__ __align__(16) __half smh[];
    __half* Ahi = smh;
    __half* Bhi = Ahi + 128 * SA;
    __half* Blo = Bhi + 128 * SA;
    __shared__ float as_s[128], ad_s[128];

    const float* X = sel_x(Xext, xsel);
    const int tid  = threadIdx.x;
    const int lane = tid & 31;
    const int wid  = tid >> 5;
    const int g    = lane >> 2;       // 0..7
    const int c    = lane & 3;        // 0..3
    const int row0 = blockIdx.x * 128;
    const int arow = wid * 16 + g;    // fragment row within tile

    if (tid < 128) { as_s[tid] = a_s[tid]; ad_s[tid] = a_d[tid]; }

    // ---- fill A tile (X fp32 -> fp16) ----
    for (int it = tid; it < 128 * 32; it += 256) {
        int r = it >> 5, j = it & 31;          // j: float4 col
        float4 v = make_float4(0.f, 0.f, 0.f, 0.f);
        if (row0 + r < NN)
            v = reinterpret_cast<const float4*>(X)[(row0 + r) * 32 + j];
        __half2 h01 = __floats2half2_rn(v.x, v.y);
        __half2 h23 = __floats2half2_rn(v.z, v.w);
        uint2 hv = make_uint2(*(uint32_t*)&h01, *(uint32_t*)&h23);
        *reinterpret_cast<uint2*>(&Ahi[r * SA + 4 * j]) = hv;
    }
    // ---- fill B tiles from preconverted g_Wt ([n][k] fp16) ----
    {
        const __half* wh = g_Wt_hi[layer];
        const __half* wl = g_Wt_lo[layer];
        for (int it = tid; it < 128 * 16; it += 256) {
            int n = it >> 4, j = it & 15;      // j: 8-half chunk
            *reinterpret_cast<uint4*>(&Bhi[n * SA + 8 * j]) =
                reinterpret_cast<const uint4*>(wh)[n * 16 + j];
            *reinterpret_cast<uint4*>(&Blo[n * SA + 8 * j]) =
                reinterpret_cast<const uint4*>(wl)[n * 16 + j];
        }
    }
    __syncthreads();

    // ---- mainloop ----
    float acc[16][4];
#pragma unroll
    for (int nt = 0; nt < 16; nt++)
#pragma unroll
        for (int q = 0; q < 4; q++) acc[nt][q] = 0.f;

#pragma unroll
    for (int ks = 0; ks < 8; ks++) {
        const int kb = ks * 16 + 2 * c;
        uint32_t ah0 = *(uint32_t*)&Ahi[arow * SA + kb];
        uint32_t ah1 = *(uint32_t*)&Ahi[(arow + 8) * SA + kb];
        uint32_t ah2 = *(uint32_t*)&Ahi[arow * SA + kb + 8];
        uint32_t ah3 = *(uint32_t*)&Ahi[(arow + 8) * SA + kb + 8];
#pragma unroll
        for (int nt = 0; nt < 16; nt++) {
            const int nrow = nt * 8 + g;
            uint32_t bh0 = *(uint32_t*)&Bhi[nrow * SA + kb];
            uint32_t bh1 = *(uint32_t*)&Bhi[nrow * SA + kb + 8];
            uint32_t bl0 = *(uint32_t*)&Blo[nrow * SA + kb];
            uint32_t bl1 = *(uint32_t*)&Blo[nrow * SA + kb + 8];
            mma16816(acc[nt], ah0, ah1, ah2, ah3, bh0, bh1);
            mma16816(acc[nt], ah0, ah1, ah2, ah3, bl0, bl1);
        }
    }

    // ---- epilogue: attn scalars from accumulators + fp16 H store ----
    float ps[2][4], pd[2][4];
#pragma unroll
    for (int r2 = 0; r2 < 2; r2++)
#pragma unroll
        for (int h = 0; h < 4; h++) { ps[r2][h] = 0.f; pd[r2][h] = 0.f; }

#pragma unroll
    for (int nt = 0; nt < 16; nt++) {
        const int head = nt >> 2;
        const int col = nt * 8 + 2 * c;
        float s0 = as_s[col], s1 = as_s[col + 1];
        float d0 = ad_s[col], d1 = ad_s[col + 1];
        ps[0][head] += acc[nt][0] * s0 + acc[nt][1] * s1;
        pd[0][head] += acc[nt][0] * d0 + acc[nt][1] * d1;
        ps[1][head] += acc[nt][2] * s0 + acc[nt][3] * s1;
        pd[1][head] += acc[nt][2] * d0 + acc[nt][3] * d1;
    }
#pragma unroll
    for (int off = 1; off <= 2; off <<= 1)
#pragma unroll
        for (int r2 = 0; r2 < 2; r2++)
#pragma unroll
            for (int h = 0; h < 4; h++) {
                ps[r2][h] += __shfl_xor_sync(0xffffffffu, ps[r2][h], off);
                pd[r2][h] += __shfl_xor_sync(0xffffffffu, pd[r2][h], off);
            }
    if (c == 0) {
        int rA = row0 + arow, rB = rA + 8;
        if (rA < NN) {
            reinterpret_cast<float4*>(g_asrc)[rA] =
                make_float4(ps[0][0], ps[0][1], ps[0][2], ps[0][3]);
            reinterpret_cast<float4*>(g_adst)[rA] =
                make_float4(pd[0][0], pd[0][1], pd[0][2], pd[0][3]);
        }
        if (rB < NN) {
            reinterpret_cast<float4*>(g_asrc)[rB] =
                make_float4(ps[1][0], ps[1][1], ps[1][2], ps[1][3]);
            reinterpret_cast<float4*>(g_adst)[rB] =
                make_float4(pd[1][0], pd[1][1], pd[1][2], pd[1][3]);
        }
    }

    {
        int rA = row0 + arow, rB = rA + 8;
#pragma unroll
        for (int nt = 0; nt < 16; nt++) {
            const int col = nt * 8 + 2 * c;
            if (rA < NN) {
                __half2 v = __floats2half2_rn(acc[nt][0], acc[nt][1]);
                *reinterpret_cast<uint32_t*>(&g_Hh[rA * 128 + col]) =
                    *reinterpret_cast<uint32_t*>(&v);
            }
            if (rB < NN) {
                __half2 v = __floats2half2_rn(acc[nt][2], acc[nt][3]);
                *reinterpret_cast<uint32_t*>(&g_Hh[rB * 128 + col]) =
                    *reinterpret_cast<uint32_t*>(&v);
            }
        }
    }
}

// ======= fused softmax + aggregate: one warp per destination node =======
// (R12 winner, verbatim.) No max pass; exp(e) cached in g_ex. Pass 2:
// half-warp per edge (16 lanes x uint4), 2 edges/iteration, LDG.128 gathers.
__global__ void __launch_bounds__(256) fused_edge(int aggsel,
                                                  const float* __restrict__ b) {
    int gw   = (blockIdx.x * blockDim.x + threadIdx.x) >> 5;
    int lane = threadIdx.x & 31;
    if (gw >= NN) return;
    const int d   = gw;
    const int beg = g_off[d];
    const int end = g_off[d + 1];   // >= beg+1 (self loop)

    float4 ad4 = reinterpret_cast<const float4*>(g_adst)[d];

    // pass 1: exp(e) per edge (cached) + per-head denominator
    float s0 = 0.f, s1 = 0.f, s2 = 0.f, s3 = 0.f;
    for (int i = beg + lane; i < end; i += 32) {
        int s = g_csr_src[i];
        float4 as = reinterpret_cast<const float4*>(g_asrc)[s];
        float x0 = __expf(fminf(lrelu(as.x + ad4.x), 30.f));
        float x1 = __expf(fminf(lrelu(as.y + ad4.y), 30.f));
        float x2 = __expf(fminf(lrelu(as.z + ad4.z), 30.f));
        float x3 = __expf(fminf(lrelu(as.w + ad4.w), 30.f));
        reinterpret_cast<float4*>(g_ex)[i] = make_float4(x0, x1, x2, x3);
        s0 += x0; s1 += x1; s2 += x2; s3 += x3;
    }
#pragma unroll
    for (int off = 16; off > 0; off >>= 1) {
        s0 += __shfl_xor_sync(0xffffffffu, s0, off);
        s1 += __shfl_xor_sync(0xffffffffu, s1, off);
        s2 += __shfl_xor_sync(0xffffffffu, s2, off);
        s3 += __shfl_xor_sync(0xffffffffu, s3, off);
    }

    __threadfence_block();   // make this warp's g_ex stores visible to all lanes
    __syncwarp();

    const int half = lane >> 4;   // 0: edge i, 1: edge i+1
    const int fl   = lane & 15;   // feature group [8*fl, 8*fl+8)
    const int hl   = fl >> 2;     // head of this feature group
    float sh = (hl & 2) ? ((hl & 1) ? s3 : s2) : ((hl & 1) ? s1 : s0);
    float rh = 1.f / (sh + 1e-16f);

    float a8[8];
#pragma unroll
    for (int j = 0; j < 8; j++) a8[j] = 0.f;

    int i = beg;
#pragma unroll 2
    for (; i + 1 < end; i += 2) {
        int idx = i + half;
        int s = g_csr_src[idx];
        float a = g_ex[idx * 4 + hl] * rh;
        uint4 hv = reinterpret_cast<const uint4*>(g_Hh)[s * 16 + fl];
        float2 f0 = __half22float2(*reinterpret_cast<__half2*>(&hv.x));
        float2 f1 = __half22float2(*reinterpret_cast<__half2*>(&hv.y));
        float2 f2 = __half22float2(*reinterpret_cast<__half2*>(&hv.z));
        float2 f3 = __half22float2(*reinterpret_cast<__half2*>(&hv.w));
        a8[0] += a * f0.x; a8[1] += a * f0.y;
        a8[2] += a * f1.x; a8[3] += a * f1.y;
        a8[4] += a * f2.x; a8[5] += a * f2.y;
        a8[6] += a * f3.x; a8[7] += a * f3.y;
    }
    if (i < end) {                  // leftover edge: only half 0 contributes
        int s = g_csr_src[i];
        float a = (half == 0) ? g_ex[i * 4 + hl] * rh : 0.f;
        uint4 hv = reinterpret_cast<const uint4*>(g_Hh)[s * 16 + fl];
        float2 f0 = __half22float2(*reinterpret_cast<__half2*>(&hv.x));
        float2 f1 = __half22float2(*reinterpret_cast<__half2*>(&hv.y));
        float2 f2 = __half22float2(*reinterpret_cast<__half2*>(&hv.z));
        float2 f3 = __half22float2(*reinterpret_cast<__half2*>(&hv.w));
        a8[0] += a * f0.x; a8[1] += a * f0.y;
        a8[2] += a * f1.x; a8[3] += a * f1.y;
        a8[4] += a * f2.x; a8[5] += a * f2.y;
        a8[6] += a * f3.x; a8[7] += a * f3.y;
    }
    // combine the two half-warps
#pragma unroll
    for (int j = 0; j < 8; j++)
        a8[j] += __shfl_xor_sync(0xffffffffu, a8[j], 16);

    if (half == 0) {
        const float4* b4 = reinterpret_cast<const float4*>(b);
        float4 b0 = b4[fl * 2], b1 = b4[fl * 2 + 1];
        float4 o0, o1;
        o0.x = fmaxf(a8[0] + b0.x, 0.f);
        o0.y = fmaxf(a8[1] + b0.y, 0.f);
        o0.z = fmaxf(a8[2] + b0.z, 0.f);
        o0.w = fmaxf(a8[3] + b0.w, 0.f);
        o1.x = fmaxf(a8[4] + b1.x, 0.f);
        o1.y = fmaxf(a8[5] + b1.y, 0.f);
        o1.z = fmaxf(a8[6] + b1.z, 0.f);
        o1.w = fmaxf(a8[7] + b1.w, 0.f);
        float4* outp =
            reinterpret_cast<float4*>(sel_buf(aggsel) + d * 128 + fl * 8);
        outp[0] = o0;
        outp[1] = o1;
    }
}

// ---------------- mean pool per graph (batch is sorted int32) ----------------
__device__ __forceinline__ int lbound_i(const int* a, int n, int v) {
    int lo = 0, hi = n;
    while (lo < hi) {
        int mid = (lo + hi) >> 1;
        if (a[mid] < v) lo = mid + 1; else hi = mid;
    }
    return lo;
}

__global__ void pool_kernel(const int* __restrict__ batch, int sel) {
    __shared__ int se[2];
    __shared__ float s[128];
    int g = blockIdx.x;
    int t = threadIdx.x;
    if (t == 0) {
        se[0] = lbound_i(batch, NN, g);
        se[1] = lbound_i(batch, NN, g + 1);
    }
    __syncthreads();
    int start = se[0], end = se[1];
    const float* h = sel_buf(sel);
    int f = t & 127;
    float acc = 0.f;
    for (int n = start + (t >> 7); n < end; n += 2)
        acc += h[n * 128 + f];
    if (t < 128) s[t] = acc;
    __syncthreads();
    if (t >= 128) s[f] += acc;   // exactly one writer per f
    __syncthreads();
    if (t < 128)
        g_pooled[g * 128 + t] = s[t] / fmaxf((float)(end - start), 1.0f);
}

// ---------------- final FC: [64,128] @ [128,10] + b ----------------
__global__ void fc_kernel(const float* __restrict__ fcW,
                          const float* __restrict__ fcb,
                          float* __restrict__ out) {
    int t = threadIdx.x;
    if (t >= NGRAPH * OUTCH) return;
    int g = t / OUTCH, o = t % OUTCH;
    float acc = fcb[o];
#pragma unroll 8
    for (int k = 0; k < 128; k++)
        acc += g_pooled[g * 128 + k] * fcW[k * OUTCH + o];
    out[t] = acc;
}

// ---------------- driver ----------------
static void run_layer(const float* x_ext, int xsel, int aggsel, int layer,
                      const float* a_s, const float* a_d, const float* b) {
    gemm_mma<<<(NN + 127) / 128, 256, GSM_BYTES>>>(x_ext, xsel, layer, a_s, a_d);
    fused_edge<<<(NN + 7) / 8, 256>>>(aggsel, b);
}

extern "C" void kernel_launch(void* const* d_in, const int* in_sizes, int n_in,
                              void* d_out, int out_size) {
    const float* x     = (const float*)d_in[0];
    const int*   ei    = (const int*)d_in[1];    // int32 (JAX x64 disabled)
    const int*   batch = (const int*)d_in[2];
    const float* W1  = (const float*)d_in[3];
    const float* a1s = (const float*)d_in[4];
    const float* a1d = (const float*)d_in[5];
    const float* b1  = (const float*)d_in[6];
    const float* W2  = (const float*)d_in[7];
    const float* a2s = (const float*)d_in[8];
    const float* a2d = (const float*)d_in[9];
    const float* b2  = (const float*)d_in[10];
    const float* W3  = (const float*)d_in[11];
    const float* a3s = (const float*)d_in[12];
    const float* a3d = (const float*)d_in[13];
    const float* b3  = (const float*)d_in[14];
    const float* fcW = (const float*)d_in[15];
    const float* fcb = (const float*)d_in[16];

    cudaFuncSetAttribute(gemm_mma, cudaFuncAttributeMaxDynamicSharedMemorySize,
                         GSM_BYTES);

    int E = in_sizes[1] / 2;
    const int* srcs = ei;
    const int* dsts = ei + E;
    int nq = (E + 3) / 4;                 // 4-edge work items
    int scat_T = nq + NN;                 // + self loops

    // W conversion (all 3 layers) + CSR build
    conv_w_all<<<(3 * FDIM * FDIM + 255) / 256, 256>>>(W1, W2, W3);
    init_deg<<<(NN + 255) / 256, 256>>>();
    count_deg4<<<(nq + 255) / 256, 256>>>(dsts, E);
    scan_p1<<<NSCB, SCB>>>();
    scan_p2<<<1, 128>>>();
    scan_p3<<<NSCB, SCB>>>();
    scatter_edges4<<<(scat_T + 255) / 256, 256>>>(srcs, dsts, E, nq);

    // layer 1: x -> P,  layer 2: P -> Q,  layer 3: Q -> P
    run_layer(x,       0, 1, 0, a1s, a1d, b1);
    run_layer(nullptr, 1, 2, 1, a2s, a2d, b2);
    run_layer(nullptr, 2, 1, 2, a3s, a3d, b3);

    pool_kernel<<<NGRAPH, 256>>>(batch, 1);
    fc_kernel<<<1, NGRAPH * OUTCH>>>(fcW, fcb, (float*)d_out);
}